// round 17
// baseline (speedup 1.0000x reference)
#include <cuda_runtime.h>
#include <cuda_fp16.h>
#include <stdint.h>
#include <math.h>

#define G_    8
#define S_    16
#define H_    512
#define BM    32          // rows per CTA
#define NT    256         // threads per CTA (8 warps, 1x8 grid)
#define CH    32768       // one B chunk: [512 n][32 k] fp16 = 32KB

// ---------------- device weight scratch (static, allowed) ----------------
__device__ __half g_W2f[G_*H_*H_];
__device__ __half g_W3f[G_*H_*H_];
__device__ __half g_W4f[G_*S_*H_];

// ---------------- smem layout (bytes) ----------------
// A  [32][256] u32 (fp16 pairs) : 0      .. 32768   (1KB per row)
// B  2 x 32KB                   : 32768  .. 98304   (xs overlays buf1; W4 tile + stg overlay buf0)
#define SM_B    32768
#define SMEM_BYTES 98304

// ---------------- helpers ----------------
__device__ __forceinline__ float swishf(float v, float sp) {
    return v * __fdividef(1.0f, 1.0f + __expf(-v * sp)) * (1.0f / 1.1f);
}
__device__ __forceinline__ float softplusf(float b) { return log1pf(__expf(b)); }

__device__ __forceinline__ uint32_t f16pair(float lo_elem, float hi_elem) {
    uint32_t r;
    asm("cvt.rn.f16x2.f32 %0, %1, %2;" : "=r"(r) : "f"(hi_elem), "f"(lo_elem));
    return r;
}

// A/W4 tile swizzled pair index (row = 256 pairs = 1KB)
__device__ __forceinline__ int a_idx(int r, int p) { return r * 256 + (p ^ ((r & 7) << 2)); }

__device__ __forceinline__ void mma16816(float* c,
    uint32_t a0, uint32_t a1, uint32_t a2, uint32_t a3, uint32_t b0, uint32_t b1) {
    asm volatile(
        "mma.sync.aligned.m16n8k16.row.col.f32.f16.f16.f32 "
        "{%0,%1,%2,%3},{%4,%5,%6,%7},{%8,%9},{%0,%1,%2,%3};"
        : "+f"(c[0]), "+f"(c[1]), "+f"(c[2]), "+f"(c[3])
        : "r"(a0), "r"(a1), "r"(a2), "r"(a3), "r"(b0), "r"(b1));
}

__device__ __forceinline__ void ldsm4(uint32_t& r0, uint32_t& r1, uint32_t& r2, uint32_t& r3,
                                      uint32_t addr) {
    asm volatile("ldmatrix.sync.aligned.m8n8.x4.shared.b16 {%0,%1,%2,%3}, [%4];"
                 : "=r"(r0), "=r"(r1), "=r"(r2), "=r"(r3) : "r"(addr));
}

template<int N> __device__ __forceinline__ void cp_wait() {
    asm volatile("cp.async.wait_group %0;" :: "n"(N) : "memory");
}

// load one B chunk [512 n][32 k] fp16 (32KB) via cp.async, swizzled rows of 64B
__device__ __forceinline__ void load_chunk(uint32_t dst_base, const __half* Wsrc,
                                           int kc, int tid) {
    #pragma unroll
    for (int l = 0; l < 8; ++l) {
        int j = tid + NT * l;           // 0..2047 16B chunks
        int n = j >> 2, q = j & 3;
        const void* src = Wsrc + (size_t)n * H_ + kc * 32 + q * 8;
        uint32_t dst = dst_base + n * 64 + ((q ^ ((n >> 1) & 3)) << 4);
        asm volatile("cp.async.cg.shared.global [%0], [%1], 16;" :: "r"(dst), "l"(src));
    }
    asm volatile("cp.async.commit_group;" ::: "memory");
}

// load W4 tile [16 n][512 k] fp16 (16KB), 1KB rows swizzled like A
__device__ __forceinline__ void load_w4(uint32_t dst_base, const __half* W4src, int tid) {
    #pragma unroll
    for (int l = 0; l < 4; ++l) {
        int j = tid + NT * l;           // 0..1023 16B chunks
        int n = j >> 6, q = j & 63;
        const void* src = W4src + (size_t)n * H_ + q * 8;
        uint32_t dst = dst_base + n * 1024 + ((q ^ (n & 7)) << 4);
        asm volatile("cp.async.cg.shared.global [%0], [%1], 16;" :: "r"(dst), "l"(src));
    }
    asm volatile("cp.async.commit_group;" ::: "memory");
}

// 16-chunk (32k each) GEMM mainloop; 2-stage pipeline, one barrier per chunk.
// Entry: chunk 0 committed into buf0.  At i==15, buf0 is free:
//   NEXT==1 -> prefetch next layer's chunk 0 there; NEXT==2 -> prefetch W4 tile.
template<int NEXT>
__device__ __forceinline__ void run_gemm(float (&acc)[2][8][4],
    uint32_t smA, uint32_t smB, const __half* W, const __half* Wn, int tid) {
    const int lane = tid & 31, wid = tid >> 5;
    const int wn = wid & 7;
    const int l7 = lane & 7;
    const uint32_t xswA = (uint32_t)(l7 << 2);            // A swizzle XOR, pair units
    const uint32_t xswB = (uint32_t)(((l7 >> 1) & 3) << 2); // B swizzle XOR, pair units
    const int mhalf = (lane >> 3) & 1;               // A: row half; B: k half
    const int kg = lane >> 4;                        // A: k group;  B: j select
    const uint32_t mhalf4 = mhalf * 4, kg4 = kg * 4;

    uint32_t aBase[2];
    #pragma unroll
    for (int mi = 0; mi < 2; ++mi)
        aBase[mi] = smA + (uint32_t)(mi * 16 + mhalf * 8 + l7) * 1024;
    uint32_t nOff[4];
    #pragma unroll
    for (int jj = 0; jj < 4; ++jj)
        nOff[jj] = (uint32_t)(wn * 64 + (2 * jj + kg) * 8 + l7) * 64;

    #pragma unroll
    for (int mi = 0; mi < 2; ++mi)
        #pragma unroll
        for (int ni = 0; ni < 8; ++ni)
            #pragma unroll
            for (int q = 0; q < 4; ++q) acc[mi][ni][q] = 0.0f;

    #pragma unroll 1
    for (int i = 0; i < 16; ++i) {
        cp_wait<0>();                    // chunk i resident
        __syncthreads();                 // + all reads of chunk i-1 complete
        if (i < 15)          load_chunk(smB + ((i + 1) & 1) * CH, W, i + 1, tid);
        else if (NEXT == 1)  load_chunk(smB, Wn, 0, tid);        // buf0 free
        else if (NEXT == 2)  load_w4(smB, Wn, tid);              // buf0 free
        const uint32_t bufB = smB + (i & 1) * CH;

        #pragma unroll
        for (int kk = 0; kk < 2; ++kk) {
            uint32_t B0[8], B1[8];
            uint32_t boff = (((uint32_t)(kk * 8) + mhalf4) ^ xswB) * 4;
            #pragma unroll
            for (int jj = 0; jj < 4; ++jj)
                ldsm4(B0[2*jj], B1[2*jj], B0[2*jj+1], B1[2*jj+1], bufB + nOff[jj] + boff);
            uint32_t aoff = (((uint32_t)(i * 16 + kk * 8) + kg4) ^ xswA) * 4;
            #pragma unroll
            for (int mi = 0; mi < 2; ++mi) {
                uint32_t a0, a1, a2, a3;
                ldsm4(a0, a1, a2, a3, aBase[mi] + aoff);
                #pragma unroll
                for (int ni = 0; ni < 8; ++ni)
                    mma16816(acc[mi][ni], a0, a1, a2, a3, B0[ni], B1[ni]);
            }
        }
    }
}

// ---------------- prep: convert W2/W3/W4 to fp16 ----------------
__global__ void prep_kernel(const float* __restrict__ W2, const float* __restrict__ W3,
                            const float* __restrict__ W4) {
    const int n = G_ * H_ * H_;
    for (int i = blockIdx.x * blockDim.x + threadIdx.x; i < n; i += gridDim.x * blockDim.x) {
        g_W2f[i] = __float2half_rn(W2[i]);
        g_W3f[i] = __float2half_rn(W3[i]);
    }
    const int m = G_ * S_ * H_;
    for (int i = blockIdx.x * blockDim.x + threadIdx.x; i < m; i += gridDim.x * blockDim.x)
        g_W4f[i] = __float2half_rn(W4[i]);
}

// ---------------- fused kernel ----------------
__global__ void __launch_bounds__(NT, 2) fused_kernel(
    const float* __restrict__ x,
    const float* __restrict__ W1, const float* __restrict__ b1, const float* __restrict__ beta1,
    const float* __restrict__ b2, const float* __restrict__ beta2,
    const float* __restrict__ b3, const float* __restrict__ beta3,
    const float* __restrict__ b4,
    float* __restrict__ out)
{
    extern __shared__ char sm[];
    uint32_t* A  = (uint32_t*)sm;
    char*     Bb = sm + SM_B;
    float*    xs = (float*)(sm + SM_B + CH);       // overlays buf1 (dead until chunk-1 load)
    const uint32_t smA = (uint32_t)__cvta_generic_to_shared(sm);
    const uint32_t smB = (uint32_t)__cvta_generic_to_shared(Bb);

    const int tid = threadIdx.x, wid = tid >> 5, lane = tid & 31;
    const int g  = blockIdx.y;
    const int b0 = blockIdx.x * BM;
    const int wn = wid & 7;                       // warp grid 1x8
    const int gq = lane >> 2, t = lane & 3;

    const __half* W2f = g_W2f + (size_t)g * H_ * H_;
    const __half* W3f = g_W3f + (size_t)g * H_ * H_;
    const __half* W4f = g_W4f + (size_t)g * S_ * H_;

    // ---- stage x tile [32x16] (stride 20) into buf1 overlay ----
    for (int i = tid; i < BM * S_; i += NT) {
        int r = i >> 4, s = i & 15;
        xs[r * 20 + s] = x[(size_t)(b0 + r) * (G_ * S_) + g * S_ + s];
    }
    __syncthreads();

    // ---- prefetch layer-2 chunk 0 (buf0; xs in buf1 untouched) ----
    load_chunk(smB, W2f, 0, tid);

    // ================= layer 1 (fp32 SIMT) -> A (fp16) =================
    {
        const float sp1 = softplusf(beta1[g]);
        const int c0 = tid * 2;                    // 256 threads cover 512 cols
        const float* w0 = W1 + ((size_t)g * H_ + c0) * S_;
        float wreg[32];
        #pragma unroll
        for (int q = 0; q < 8; ++q) {
            float4 v = *(const float4*)(w0 + q * 4);
            wreg[q * 4 + 0] = v.x; wreg[q * 4 + 1] = v.y;
            wreg[q * 4 + 2] = v.z; wreg[q * 4 + 3] = v.w;
        }
        const float bb0 = b1[(size_t)g * H_ + c0];
        const float bb1 = b1[(size_t)g * H_ + c0 + 1];
        for (int r = 0; r < BM; ++r) {
            const float* xr = xs + r * 20;
            float v0 = bb0, v1 = bb1;
            #pragma unroll
            for (int q = 0; q < 4; ++q) {
                float4 xv = *(const float4*)(xr + q * 4);
                v0 = fmaf(xv.x, wreg[q*4+0], v0); v1 = fmaf(xv.x, wreg[16+q*4+0], v1);
                v0 = fmaf(xv.y, wreg[q*4+1], v0); v1 = fmaf(xv.y, wreg[16+q*4+1], v1);
                v0 = fmaf(xv.z, wreg[q*4+2], v0); v1 = fmaf(xv.z, wreg[16+q*4+2], v1);
                v0 = fmaf(xv.w, wreg[q*4+3], v0); v1 = fmaf(xv.w, wreg[16+q*4+3], v1);
            }
            v0 = swishf(v0, sp1);
            v1 = swishf(v1, sp1);
            A[a_idx(r, tid)] = f16pair(v0, v1);
        }
    }
    __syncthreads();

    float acc[2][8][4];

    // ================= layer 2 (fp16 HMMA) — tail-prefetches W3 chunk 0 =================
    run_gemm<1>(acc, smA, smB, W2f, W3f, tid);
    __syncthreads();                                  // all A + chunk-15 reads done

    // layer-2 epilogue: bias + swish -> fp16 -> rewrite A
    {
        const float sp2 = softplusf(beta2[g]);
        const float* bg = b2 + (size_t)g * H_;
        #pragma unroll
        for (int ni = 0; ni < 8; ++ni) {
            int cb = wn * 64 + ni * 8 + 2 * t;
            float be = __ldg(bg + cb), bo = __ldg(bg + cb + 1);
            int p = wn * 32 + ni * 4 + t;
            #pragma unroll
            for (int mi = 0; mi < 2; ++mi) {
                int r0 = mi * 16 + gq;
                float v00 = swishf(acc[mi][ni][0] + be, sp2);
                float v01 = swishf(acc[mi][ni][1] + bo, sp2);
                float v10 = swishf(acc[mi][ni][2] + be, sp2);
                float v11 = swishf(acc[mi][ni][3] + bo, sp2);
                A[a_idx(r0, p)]     = f16pair(v00, v01);
                A[a_idx(r0 + 8, p)] = f16pair(v10, v11);
            }
        }
    }
    __syncthreads();

    // ================= layer 3 (fp16 HMMA) — tail-prefetches W4 tile =================
    run_gemm<2>(acc, smA, smB, W3f, W4f, tid);
    __syncthreads();                                  // all A + chunk-15 reads done

    // layer-3 epilogue: bias + swish -> fp16 -> rewrite A (h3)
    {
        const float sp3 = softplusf(beta3[g]);
        const float* bg = b3 + (size_t)g * H_;
        #pragma unroll
        for (int ni = 0; ni < 8; ++ni) {
            int cb = wn * 64 + ni * 8 + 2 * t;
            float be = __ldg(bg + cb), bo = __ldg(bg + cb + 1);
            int p = wn * 32 + ni * 4 + t;
            #pragma unroll
            for (int mi = 0; mi < 2; ++mi) {
                int r0 = mi * 16 + gq;
                float v00 = swishf(acc[mi][ni][0] + be, sp3);
                float v01 = swishf(acc[mi][ni][1] + bo, sp3);
                float v10 = swishf(acc[mi][ni][2] + be, sp3);
                float v11 = swishf(acc[mi][ni][3] + bo, sp3);
                A[a_idx(r0, p)]     = f16pair(v00, v01);
                A[a_idx(r0 + 8, p)] = f16pair(v10, v11);
            }
        }
    }
    cp_wait<0>();          // W4 tile resident (prefetched in layer-3 tail)
    __syncthreads();       // + h3 writes visible

    // ================= layer 4 (fp16 HMMA, k split over wn) =================
    {
        const int l7 = lane & 7;
        const uint32_t xsw = (uint32_t)(l7 << 2);
        const int khalf = (lane >> 3) & 1;
        const int ntile = lane >> 4;
        const uint32_t khalf4 = khalf * 4, kg4 = ntile * 4;   // A reuses same lane roles

        float a4[2][2][4];
        #pragma unroll
        for (int mi = 0; mi < 2; ++mi)
            #pragma unroll
            for (int ni = 0; ni < 2; ++ni)
                #pragma unroll
                for (int q = 0; q < 4; ++q) a4[mi][ni][q] = 0.0f;

        uint32_t aBase[2];
        #pragma unroll
        for (int mi = 0; mi < 2; ++mi)
            aBase[mi] = smA + (uint32_t)(mi * 16 + khalf * 8 + l7) * 1024;
        const uint32_t bRow = smB + (uint32_t)(ntile * 8 + l7) * 1024;  // W4 row n

        #pragma unroll
        for (int kk = 0; kk < 4; ++kk) {
            uint32_t pb = (uint32_t)(wn * 32 + kk * 8);
            uint32_t B0[2], B1[2];
            ldsm4(B0[0], B1[0], B0[1], B1[1], bRow + ((pb + khalf4) ^ xsw) * 4);
            uint32_t aoff = ((pb + kg4) ^ xsw) * 4;
            #pragma unroll
            for (int mi = 0; mi < 2; ++mi) {
                uint32_t a0, a1, a2, a3;
                ldsm4(a0, a1, a2, a3, aBase[mi] + aoff);
                #pragma unroll
                for (int ni = 0; ni < 2; ++ni)
                    mma16816(a4[mi][ni], a0, a1, a2, a3, B0[ni], B1[ni]);
            }
        }

        // stage per-wn partials: [8 wn][32 rows][16 cols] f32 (16KB) after W4 tile (16KB)
        float* stg = (float*)(Bb + 16384);
        #pragma unroll
        for (int mi = 0; mi < 2; ++mi) {
            int r0 = mi * 16 + gq;
            #pragma unroll
            for (int ni = 0; ni < 2; ++ni) {
                int c = ni * 8 + 2 * t;
                stg[(wn * 32 + r0) * 16 + c]         = a4[mi][ni][0];
                stg[(wn * 32 + r0) * 16 + c + 1]     = a4[mi][ni][1];
                stg[(wn * 32 + r0 + 8) * 16 + c]     = a4[mi][ni][2];
                stg[(wn * 32 + r0 + 8) * 16 + c + 1] = a4[mi][ni][3];
            }
        }
        __syncthreads();
        // final: sum 8 wn-partials + b4, write out (2 outputs per thread)
        {
            int r = tid >> 3, s0 = (tid & 7) * 2;
            float o0 = b4[(size_t)g * S_ + s0];
            float o1 = b4[(size_t)g * S_ + s0 + 1];
            #pragma unroll
            for (int w = 0; w < 8; ++w) {
                float2 v = *(const float2*)(stg + (w * 32 + r) * 16 + s0);
                o0 += v.x; o1 += v.y;
            }
            *(float2*)&out[(size_t)(b0 + r) * (G_ * S_) + g * S_ + s0] = make_float2(o0, o1);
        }
    }
}

// ================= launch =================
extern "C" void kernel_launch(void* const* d_in, const int* in_sizes, int n_in,
                              void* d_out, int out_size) {
    const float* x     = (const float*)d_in[0];
    const float* W1    = (const float*)d_in[1];
    const float* b1    = (const float*)d_in[2];
    const float* beta1 = (const float*)d_in[3];
    const float* W2    = (const float*)d_in[4];
    const float* b2    = (const float*)d_in[5];
    const float* beta2 = (const float*)d_in[6];
    const float* W3    = (const float*)d_in[7];
    const float* b3    = (const float*)d_in[8];
    const float* beta3 = (const float*)d_in[9];
    const float* W4    = (const float*)d_in[10];
    const float* b4    = (const float*)d_in[11];
    float* out = (float*)d_out;

    int Brows = in_sizes[0] / (G_ * S_);

    cudaFuncSetAttribute(fused_kernel, cudaFuncAttributeMaxDynamicSharedMemorySize, SMEM_BYTES);

    prep_kernel<<<512, 256>>>(W2, W3, W4);

    dim3 grid(Brows / BM, G_);
    fused_kernel<<<grid, NT, SMEM_BYTES>>>(x, W1, b1, beta1, b2, beta2, b3, beta3, b4, out);
}